// round 2
// baseline (speedup 1.0000x reference)
#include <cuda_runtime.h>

#define N_NODES 100000
#define N_EDGES 3200000
#define C_DIM   256
#define NEG_SLOPE 0.2f

// Scratch (allocation-free): node score arrays + softmax denominator.
__device__ float g_s_src[N_NODES];
__device__ float g_s_dst[N_NODES];
__device__ float g_denom[N_NODES];

// ---------------------------------------------------------------------------
// Kernel 1: per-node scores s_src = x·att[:C], s_dst = x·att[C:], zero denom.
// One warp per node. Fully coalesced float4 loads of x (102.4 MB streamed).
// ---------------------------------------------------------------------------
__global__ void __launch_bounds__(256)
node_scores_kernel(const float* __restrict__ x, const float* __restrict__ att) {
    int gtid = blockIdx.x * blockDim.x + threadIdx.x;
    int node = gtid >> 5;
    int lane = threadIdx.x & 31;
    if (node >= N_NODES) return;

    const float4* xr = reinterpret_cast<const float4*>(x + (size_t)node * C_DIM);
    const float4* a0 = reinterpret_cast<const float4*>(att);          // att[:C]
    const float4* a1 = reinterpret_cast<const float4*>(att + C_DIM);  // att[C:]

    float s0 = 0.f, s1 = 0.f;
#pragma unroll
    for (int i = 0; i < 2; ++i) {
        int idx = lane + 32 * i;          // 64 float4 per row
        float4 xv = xr[idx];
        float4 av = a0[idx];
        float4 bv = a1[idx];
        s0 += xv.x * av.x + xv.y * av.y + xv.z * av.z + xv.w * av.w;
        s1 += xv.x * bv.x + xv.y * bv.y + xv.z * bv.z + xv.w * bv.w;
    }
#pragma unroll
    for (int off = 16; off; off >>= 1) {
        s0 += __shfl_down_sync(0xffffffffu, s0, off);
        s1 += __shfl_down_sync(0xffffffffu, s1, off);
    }
    if (lane == 0) {
        g_s_src[node] = s0;
        g_s_dst[node] = s1;
        g_denom[node] = 0.f;
    }
}

// ---------------------------------------------------------------------------
// Kernel 2: per-edge e = exp(leaky_relu(s_src[row] + s_dst[col])).
// Max-shift dropped: exp(a)/sum(exp(a)) is mathematically identical and
// |a| <= ~8 here, so fp32 is safe. Writes e to out, accumulates denom[row].
// 4 edges per thread; int4 index loads. s arrays (800 KB) are L2-resident.
// ---------------------------------------------------------------------------
__global__ void __launch_bounds__(256)
edge_exp_kernel(const int* __restrict__ row,
                const int* __restrict__ col,
                float* __restrict__ out) {
    int i = blockIdx.x * blockDim.x + threadIdx.x;   // quad index
    if (i * 4 >= N_EDGES) return;

    int4 r4 = reinterpret_cast<const int4*>(row)[i];
    int4 c4 = reinterpret_cast<const int4*>(col)[i];

    float a0 = g_s_src[r4.x] + g_s_dst[c4.x];
    float a1 = g_s_src[r4.y] + g_s_dst[c4.y];
    float a2 = g_s_src[r4.z] + g_s_dst[c4.z];
    float a3 = g_s_src[r4.w] + g_s_dst[c4.w];
    a0 = a0 > 0.f ? a0 : NEG_SLOPE * a0;
    a1 = a1 > 0.f ? a1 : NEG_SLOPE * a1;
    a2 = a2 > 0.f ? a2 : NEG_SLOPE * a2;
    a3 = a3 > 0.f ? a3 : NEG_SLOPE * a3;
    float e0 = __expf(a0);
    float e1 = __expf(a1);
    float e2 = __expf(a2);
    float e3 = __expf(a3);

    reinterpret_cast<float4*>(out)[i] = make_float4(e0, e1, e2, e3);
    atomicAdd(&g_denom[r4.x], e0);
    atomicAdd(&g_denom[r4.y], e1);
    atomicAdd(&g_denom[r4.z], e2);
    atomicAdd(&g_denom[r4.w], e3);
}

// ---------------------------------------------------------------------------
// Kernel 3: denom -> 1/denom (tiny). Nodes with no in-edges give inf, never read.
// ---------------------------------------------------------------------------
__global__ void __launch_bounds__(256)
inv_kernel() {
    int i = blockIdx.x * blockDim.x + threadIdx.x;
    if (i < N_NODES) g_denom[i] = __frcp_rn(g_denom[i]);
}

// ---------------------------------------------------------------------------
// Kernel 4: out[e] *= denom_inv[row[e]].  denom (400 KB) is L2-resident.
// ---------------------------------------------------------------------------
__global__ void __launch_bounds__(256)
normalize_kernel(const int* __restrict__ row, float* __restrict__ out) {
    int i = blockIdx.x * blockDim.x + threadIdx.x;   // quad index
    if (i * 4 >= N_EDGES) return;

    int4 r4 = reinterpret_cast<const int4*>(row)[i];
    float4 v = reinterpret_cast<float4*>(out)[i];
    v.x *= g_denom[r4.x];
    v.y *= g_denom[r4.y];
    v.z *= g_denom[r4.z];
    v.w *= g_denom[r4.w];
    reinterpret_cast<float4*>(out)[i] = v;
}

// ---------------------------------------------------------------------------
extern "C" void kernel_launch(void* const* d_in, const int* in_sizes, int n_in,
                              void* d_out, int out_size) {
    const float* x    = (const float*)d_in[0];   // (N, C) f32
    const float* att  = (const float*)d_in[1];   // (2C, 1) f32
    const int*   edge = (const int*)d_in[2];     // (2, E) int32 (JAX x64 disabled)
    float*       out  = (float*)d_out;           // (1, E) f32

    const int* row = edge;             // edge_index[0]
    const int* col = edge + N_EDGES;   // edge_index[1]

    {
        int threads = 256;
        int blocks = (N_NODES * 32 + threads - 1) / threads;
        node_scores_kernel<<<blocks, threads>>>(x, att);
    }
    {
        int threads = 256;
        int blocks = (N_EDGES / 4 + threads - 1) / threads;
        edge_exp_kernel<<<blocks, threads>>>(row, col, out);
    }
    {
        int threads = 256;
        int blocks = (N_NODES + threads - 1) / threads;
        inv_kernel<<<blocks, threads>>>();
    }
    {
        int threads = 256;
        int blocks = (N_EDGES / 4 + threads - 1) / threads;
        normalize_kernel<<<blocks, threads>>>(row, out);
    }
}